// round 14
// baseline (speedup 1.0000x reference)
#include <cuda_runtime.h>
#include <cuda_fp16.h>
#include <cstdint>

#define SEQ 2048
#define DIM 1024
#define DH  64
#define HB  32
#define NB  2
#define THR 256

// ---------------- scratch (static __device__, allocation-free) --------------
static __device__ __half g_Xh[4096*1024], g_Xl[4096*1024];
static __device__ __half g_Wth[3*1024*1024], g_Wtl[3*1024*1024];   // [z][n][k]
static __device__ __half g_Qh[HB*SEQ*DH], g_Ql[HB*SEQ*DH];         // [hb][s][dh]
static __device__ __half g_Kh[HB*SEQ*DH], g_Kl[HB*SEQ*DH];
static __device__ __half g_Vh[HB*SEQ*DH];

// ---------------- helpers ---------------------------------------------------
__device__ __forceinline__ uint32_t s2u(const void* p){
    uint32_t a;
    asm("{ .reg .u64 t; cvta.to.shared.u64 t, %1; cvt.u32.u64 %0, t; }" : "=r"(a) : "l"(p));
    return a;
}
#define CPA(s,g) asm volatile("cp.async.cg.shared.global [%0], [%1], 16;" :: "r"(s), "l"(g))
#define CPA_COMMIT() asm volatile("cp.async.commit_group;" ::: "memory")
#define CPA_WAIT(n)  asm volatile("cp.async.wait_group %0;" :: "n"(n) : "memory")

__device__ __forceinline__ void ldsm4(uint32_t* r, uint32_t a){
    asm volatile("ldmatrix.sync.aligned.m8n8.x4.shared.b16 {%0,%1,%2,%3}, [%4];"
        : "=r"(r[0]), "=r"(r[1]), "=r"(r[2]), "=r"(r[3]) : "r"(a));
}
__device__ __forceinline__ void ldsm4t(uint32_t* r, uint32_t a){
    asm volatile("ldmatrix.sync.aligned.m8n8.x4.trans.shared.b16 {%0,%1,%2,%3}, [%4];"
        : "=r"(r[0]), "=r"(r[1]), "=r"(r[2]), "=r"(r[3]) : "r"(a));
}
__device__ __forceinline__ void mma16816(float* c, const uint32_t* a, uint32_t b0, uint32_t b1){
    asm volatile("mma.sync.aligned.m16n8k16.row.col.f32.f16.f16.f32 "
        "{%0,%1,%2,%3}, {%4,%5,%6,%7}, {%8,%9}, {%0,%1,%2,%3};"
        : "+f"(c[0]), "+f"(c[1]), "+f"(c[2]), "+f"(c[3])
        : "r"(a[0]), "r"(a[1]), "r"(a[2]), "r"(a[3]), "r"(b0), "r"(b1));
}
__device__ __forceinline__ uint32_t swa(uint32_t base, int r, int cb){
    uint32_t off = (uint32_t)r * 128u + (uint32_t)cb;
    return base + (off ^ ((off >> 3) & 0x70));
}
__device__ __forceinline__ void split2(float x, float y, uint32_t& hi, uint32_t& lo){
    __half hx = __float2half_rn(x), hy = __float2half_rn(y);
    __half lx = __float2half_rn(x - __half2float(hx));
    __half ly = __float2half_rn(y - __half2float(hy));
    __half2 H = __halves2half2(hx, hy), L = __halves2half2(lx, ly);
    hi = *(uint32_t*)&H; lo = *(uint32_t*)&L;
}
__device__ __forceinline__ void fsplit(float x, __half& h, __half& l){
    h = __float2half_rn(x);
    l = __float2half_rn(x - __half2float(h));
}
__device__ __forceinline__ uint32_t pack_h2(float x, float y){
    __half2 p = __floats2half2_rn(x, y);
    return *(uint32_t*)&p;
}
__device__ __forceinline__ void load_tile(uint32_t sdst, const __half* g,
                                          int rows, int gstride){
    for (int i = threadIdx.x; i < rows * 8; i += THR){
        int r = i >> 3, c = i & 7;
        uint32_t off = (uint32_t)r * 128u + (uint32_t)c * 16u;
        uint32_t sw  = off ^ ((off >> 3) & 0x70);
        CPA(sdst + sw, (const char*)(g + (size_t)r * gstride) + c * 16);
    }
}

// ---------------- prep ------------------------------------------------------
__global__ void __launch_bounds__(256) k_splitX(const float4* __restrict__ X){
    int i = blockIdx.x * 256 + threadIdx.x;
    float4 v = X[i];
    uint32_t h0, l0, h1, l1;
    split2(v.x, v.y, h0, l0);
    split2(v.z, v.w, h1, l1);
    ((uint2*)g_Xh)[i] = make_uint2(h0, h1);
    ((uint2*)g_Xl)[i] = make_uint2(l0, l1);
}

__global__ void __launch_bounds__(256) k_splitW(const float* __restrict__ Wq,
                                                const float* __restrict__ Wk,
                                                const float* __restrict__ Wv){
    const int z = blockIdx.z;
    const float* __restrict__ W = (z == 0) ? Wq : (z == 1) ? Wk : Wv;
    __shared__ float t[32][33];
    int tx = threadIdx.x, ty = threadIdx.y;      // (32,8)
    int bx = blockIdx.x * 32, by = blockIdx.y * 32;
#pragma unroll
    for (int i = 0; i < 32; i += 8)
        t[ty + i][tx] = W[(size_t)(by + ty + i) * DIM + bx + tx];
    __syncthreads();
#pragma unroll
    for (int i = 0; i < 32; i += 8){
        int n = bx + ty + i, k = by + tx;
        __half h, l; fsplit(t[tx][ty + i], h, l);
        size_t o = (size_t)z * DIM * DIM + (size_t)n * DIM + k;
        g_Wth[o] = h; g_Wtl[o] = l;
    }
}

// ---------------- QKV: 128x64 CTA tile, 32x32 warp tile, 2-stage ------------
#define QKV_STAGE 49152
#define QKV_SMEM  (2 * QKV_STAGE)
__global__ void __launch_bounds__(256, 2) k_qkv_mma(){
    extern __shared__ __align__(1024) char smraw[];
    uint32_t sbase = s2u(smraw);
    const int tid = threadIdx.x, w = tid >> 5, lane = tid & 31;
    const int z  = blockIdx.z;
    const int bm = blockIdx.y * 128;
    const int bn = blockIdx.x * 64;

    const __half* Ah = g_Xh + (size_t)bm * DIM;
    const __half* Al = g_Xl + (size_t)bm * DIM;
    const __half* Bh = g_Wth + (size_t)z * DIM * DIM + (size_t)bn * DIM;
    const __half* Bl = g_Wtl + (size_t)z * DIM * DIM + (size_t)bn * DIM;

    float c[2][4][4];
#pragma unroll
    for (int a = 0; a < 2; a++)
#pragma unroll
        for (int b = 0; b < 4; b++)
#pragma unroll
            for (int d = 0; d < 4; d++) c[a][b][d] = 0.f;

    const int m0 = (w & 3) * 32, n0 = (w >> 2) * 32;
    const int NT = DIM / 64;   // 16
    const bool full = (z < 2);   // V tolerates 2-term split

    auto stage_load = [&](int kt){
        uint32_t buf = sbase + (uint32_t)(kt & 1) * QKV_STAGE;
        load_tile(buf,         Ah + kt * 64, 128, DIM);
        load_tile(buf + 16384, Al + kt * 64, 128, DIM);
        load_tile(buf + 32768, Bh + kt * 64,  64, DIM);
        load_tile(buf + 40960, Bl + kt * 64,  64, DIM);
    };
    stage_load(0); CPA_COMMIT();
    stage_load(1); CPA_COMMIT();

    for (int kt = 0; kt < NT; kt++){
        CPA_WAIT(1);
        __syncthreads();
        uint32_t buf = sbase + (uint32_t)(kt & 1) * QKV_STAGE;
        const uint32_t sAh = buf, sAl = buf + 16384;
        const uint32_t sBh = buf + 32768, sBl = buf + 40960;
#pragma unroll
        for (int kk = 0; kk < 4; kk++){
            uint32_t aH[2][4], aL[2][4];
            int cb = kk * 32 + (lane >> 4) * 16;
#pragma unroll
            for (int mt = 0; mt < 2; mt++){
                int rr = m0 + mt * 16 + (lane & 15);
                ldsm4(aH[mt], swa(sAh, rr, cb));
                ldsm4(aL[mt], swa(sAl, rr, cb));
            }
#pragma unroll
            for (int nt = 0; nt < 2; nt++){
                uint32_t bH[4], bL[4];
                int rr = n0 + nt * 16 + (lane & 15);
                ldsm4(bH, swa(sBh, rr, cb));
                ldsm4(bL, swa(sBl, rr, cb));
#pragma unroll
                for (int mt = 0; mt < 2; mt++){
                    mma16816(c[mt][2*nt],   aH[mt], bH[0], bH[2]);
                    mma16816(c[mt][2*nt+1], aH[mt], bH[1], bH[3]);
                    mma16816(c[mt][2*nt],   aH[mt], bL[0], bL[2]);
                    mma16816(c[mt][2*nt+1], aH[mt], bL[1], bL[3]);
                    if (full){
                        mma16816(c[mt][2*nt],   aL[mt], bH[0], bH[2]);
                        mma16816(c[mt][2*nt+1], aL[mt], bH[1], bH[3]);
                    }
                }
            }
        }
        __syncthreads();
        if (kt + 2 < NT) stage_load(kt + 2);
        CPA_COMMIT();
    }

    // Q gets 0.125 * log2(e) so flash can use exp2 directly.
    const float sc = (z == 0) ? 0.125f * 1.4426950408889634f : 1.0f;
#pragma unroll
    for (int mt = 0; mt < 2; mt++){
#pragma unroll
        for (int nt = 0; nt < 4; nt++){
            int n = bn + n0 + nt * 8 + (lane & 3) * 2;
            int h = n >> 6, d = n & 63;
#pragma unroll
            for (int half = 0; half < 2; half++){
                int m = bm + m0 + mt * 16 + (lane >> 2) + half * 8;
                int bb = m >> 11, s = m & (SEQ - 1);
                size_t o = ((size_t)(h * NB + bb) * SEQ + s) * DH + d;
                if (z == 2){
                    *(uint32_t*)(g_Vh + o) = pack_h2(c[mt][nt][half*2], c[mt][nt][half*2+1]);
                } else {
                    uint32_t hi, lo;
                    split2(c[mt][nt][half*2] * sc, c[mt][nt][half*2+1] * sc, hi, lo);
                    __half* Gh = (z == 0) ? g_Qh : g_Kh;
                    __half* Gl = (z == 0) ? g_Ql : g_Kl;
                    *(uint32_t*)(Gh + o) = hi;
                    *(uint32_t*)(Gl + o) = lo;
                }
            }
        }
    }
}

// ---------------- fused flash: 64 q-rows, 128-key tiles, 2 CTAs/SM ----------
// Warp (wq,wg): q rows [wq*16,+16), keys [wg*64,+64) of each 128-key tile.
// 16 tiles; split-K merge across wg pairs at the end.
#define FA_STAGE 49152
#define FA_SMEM  (16384 + 2 * FA_STAGE)
__global__ void __launch_bounds__(256, 2) k_flash(float* __restrict__ out){
    extern __shared__ __align__(1024) char smraw[];
    uint32_t sbase = s2u(smraw);
    const int tid = threadIdx.x, w = tid >> 5, lane = tid & 31;
    const int wq = w & 3, wg = w >> 2;
    const int z  = blockIdx.y;
    const int bm = blockIdx.x * 64;

    const uint32_t sQh = sbase, sQl = sbase + 8192;
    const uint32_t stg = sbase + 16384;
    const uint32_t ONES = 0x3C003C00u;   // half2(1.0, 1.0)

    const __half* Kh = g_Kh + (size_t)z * SEQ * DH;
    const __half* Kl = g_Kl + (size_t)z * SEQ * DH;
    const __half* Vh = g_Vh + (size_t)z * SEQ * DH;

    auto stage_load = [&](int kt){
        uint32_t buf = stg + (uint32_t)(kt & 1) * FA_STAGE;
        load_tile(buf,         Kh + (size_t)kt * 128 * DH, 128, DH);
        load_tile(buf + 16384, Kl + (size_t)kt * 128 * DH, 128, DH);
        load_tile(buf + 32768, Vh + (size_t)kt * 128 * DH, 128, DH);
    };
    load_tile(sQh, g_Qh + ((size_t)z * SEQ + bm) * DH, 64, DH);
    load_tile(sQl, g_Ql + ((size_t)z * SEQ + bm) * DH, 64, DH);
    stage_load(0); CPA_COMMIT();
    stage_load(1); CPA_COMMIT();

    float co[8][4];
#pragma unroll
    for (int i = 0; i < 8; i++)
#pragma unroll
        for (int j = 0; j < 4; j++) co[i][j] = 0.f;
    float cl[4] = {0.f, 0.f, 0.f, 0.f};
    float m0 = -1e30f, m1 = -1e30f;

    uint32_t qH[4][4];   // hoisted Q hi fragments

    const int NT = SEQ / 128;   // 16
    for (int kt = 0; kt < NT; kt++){
        CPA_WAIT(1);
        __syncthreads();

        if (kt == 0){
#pragma unroll
            for (int kk = 0; kk < 4; kk++){
                int rr = wq * 16 + (lane & 15);
                int cb = kk * 32 + (lane >> 4) * 16;
                ldsm4(qH[kk], swa(sQh, rr, cb));
            }
        }

        uint32_t bufC = stg + (uint32_t)(kt & 1) * FA_STAGE;
        const uint32_t sKh = bufC, sKl = bufC + 16384;
        const uint32_t sVh = bufC + 32768;

        // ---- S = Q @ K^T (16 q-rows x 64 keys per warp, 3-term fp32) ----
        float cs[8][4];
#pragma unroll
        for (int t = 0; t < 8; t++)
#pragma unroll
            for (int j = 0; j < 4; j++) cs[t][j] = 0.f;
#pragma unroll
        for (int kk = 0; kk < 4; kk++){
            uint32_t qL[4];
            {
                int rr = wq * 16 + (lane & 15);
                int cb = kk * 32 + (lane >> 4) * 16;
                ldsm4(qL, swa(sQl, rr, cb));
            }
#pragma unroll
            for (int nq = 0; nq < 4; nq++){
                uint32_t bH[4], bL[4];
                int rr = wg * 64 + nq * 16 + (lane & 15);
                int cb = kk * 32 + (lane >> 4) * 16;
                ldsm4(bH, swa(sKh, rr, cb));
                ldsm4(bL, swa(sKl, rr, cb));
                mma16816(cs[2*nq],   qH[kk], bH[0], bH[2]);
                mma16816(cs[2*nq+1], qH[kk], bH[1], bH[3]);
                mma16816(cs[2*nq],   qH[kk], bL[0], bL[2]);
                mma16816(cs[2*nq+1], qH[kk], bL[1], bL[3]);
                mma16816(cs[2*nq],   qL,     bH[0], bH[2]);
                mma16816(cs[2*nq+1], qL,     bH[1], bH[3]);
            }
        }

        // ---- online softmax in base-2 (rows r0=lane>>2, r1=r0+8) ----
        float mx0 = -1e30f, mx1 = -1e30f;
#pragma unroll
        for (int t = 0; t < 8; t++){
            mx0 = fmaxf(mx0, fmaxf(cs[t][0], cs[t][1]));
            mx1 = fmaxf(mx1, fmaxf(cs[t][2], cs[t][3]));
        }
        mx0 = fmaxf(mx0, __shfl_xor_sync(0xffffffffu, mx0, 1));
        mx0 = fmaxf(mx0, __shfl_xor_sync(0xffffffffu, mx0, 2));
        mx1 = fmaxf(mx1, __shfl_xor_sync(0xffffffffu, mx1, 1));
        mx1 = fmaxf(mx1, __shfl_xor_sync(0xffffffffu, mx1, 2));

        float mn0 = fmaxf(m0, mx0), mn1 = fmaxf(m1, mx1);
        bool same = (mn0 == m0) && (mn1 == m1);
        if (!__all_sync(0xffffffffu, same)){
            float sc0 = exp2f(m0 - mn0), sc1 = exp2f(m1 - mn1);
            m0 = mn0; m1 = mn1;
            cl[0] *= sc0; cl[2] *= sc1;
#pragma unroll
            for (int nt = 0; nt < 8; nt++){
                co[nt][0] *= sc0; co[nt][1] *= sc0;
                co[nt][2] *= sc1; co[nt][3] *= sc1;
            }
        }

#pragma unroll
        for (int t = 0; t < 8; t++){
            cs[t][0] = exp2f(cs[t][0] - m0);
            cs[t][1] = exp2f(cs[t][1] - m0);
            cs[t][2] = exp2f(cs[t][2] - m1);
            cs[t][3] = exp2f(cs[t][3] - m1);
        }

        // ---- O += P(fp16) @ V(fp16); l += P @ ones ----
#pragma unroll
        for (int kc = 0; kc < 4; kc++){
            uint32_t aP[4];
            aP[0] = pack_h2(cs[2*kc][0],   cs[2*kc][1]);
            aP[1] = pack_h2(cs[2*kc][2],   cs[2*kc][3]);
            aP[2] = pack_h2(cs[2*kc+1][0], cs[2*kc+1][1]);
            aP[3] = pack_h2(cs[2*kc+1][2], cs[2*kc+1][3]);
            mma16816(cl, aP, ONES, ONES);
#pragma unroll
            for (int nq = 0; nq < 4; nq++){
                uint32_t bH[4];
                int rr = wg * 64 + kc * 16 + ((lane >> 4) & 1) * 8 + (lane & 7);
                int cb = (nq * 16 + ((lane >> 3) & 1) * 8) * 2;
                ldsm4t(bH, swa(sVh, rr, cb));
                mma16816(co[2*nq],   aP, bH[0], bH[2]);
                mma16816(co[2*nq+1], aP, bH[1], bH[3]);
            }
        }

        __syncthreads();
        if (kt + 2 < NT) stage_load(kt + 2);
        CPA_COMMIT();
    }

    float l0 = cl[0], l1 = cl[2];

    // ---- split-K merge across wg pairs (exchange via smem) ----
    CPA_WAIT(0);
    __syncthreads();
    float* ex = (float*)smraw;
    float* p = ex + ((size_t)(wq * 32 + lane)) * 37;
    if (wg == 1){
#pragma unroll
        for (int i = 0; i < 8; i++)
#pragma unroll
            for (int j = 0; j < 4; j++) p[i*4 + j] = co[i][j];
        p[32] = m0; p[33] = m1; p[34] = l0; p[35] = l1;
    }
    __syncthreads();
    if (wg == 0){
        float m0b = p[32], m1b = p[33], l0b = p[34], l1b = p[35];
        float mm0 = fmaxf(m0, m0b), mm1 = fmaxf(m1, m1b);
        float a0 = exp2f(m0 - mm0), b0 = exp2f(m0b - mm0);
        float a1 = exp2f(m1 - mm1), b1 = exp2f(m1b - mm1);
        float inv0 = 1.f / (l0 * a0 + l0b * b0);
        float inv1 = 1.f / (l1 * a1 + l1b * b1);

        const int r0 = bm + wq * 16 + (lane >> 2);
#pragma unroll
        for (int nt = 0; nt < 8; nt++){
            int n = nt * 8 + (lane & 3) * 2;
            float* d0 = out + ((size_t)z * SEQ + r0) * DH + n;
            float* d1 = out + ((size_t)z * SEQ + r0 + 8) * DH + n;
            float o00 = (co[nt][0] * a0 + p[nt*4+0] * b0) * inv0;
            float o01 = (co[nt][1] * a0 + p[nt*4+1] * b0) * inv0;
            float o10 = (co[nt][2] * a1 + p[nt*4+2] * b1) * inv1;
            float o11 = (co[nt][3] * a1 + p[nt*4+3] * b1) * inv1;
            *(float2*)d0 = make_float2(o00, o01);
            *(float2*)d1 = make_float2(o10, o11);
        }
    }
}

// ---------------------------------------------------------------------------
extern "C" void kernel_launch(void* const* d_in, const int* in_sizes, int n_in,
                              void* d_out, int out_size)
{
    const float* X  = (const float*)d_in[0];
    const float* Wq = (const float*)d_in[1];
    const float* Wk = (const float*)d_in[2];
    const float* Wv = (const float*)d_in[3];
    float* out = (float*)d_out;

    cudaFuncSetAttribute(k_qkv_mma, cudaFuncAttributeMaxDynamicSharedMemorySize, QKV_SMEM);
    cudaFuncSetAttribute(k_flash,   cudaFuncAttributeMaxDynamicSharedMemorySize, FA_SMEM);

    k_splitX <<<4096, 256>>>((const float4*)X);
    k_splitW <<<dim3(32, 32, 3), dim3(32, 8)>>>(Wq, Wk, Wv);
    k_qkv_mma<<<dim3(16, 32, 3), THR, QKV_SMEM>>>();
    k_flash  <<<dim3(SEQ / 64, HB), THR, FA_SMEM>>>(out);
}

// round 15
// speedup vs baseline: 1.5429x; 1.5429x over previous
#include <cuda_runtime.h>
#include <cuda_fp16.h>
#include <cstdint>

#define SEQ 2048
#define DIM 1024
#define DH  64
#define HB  32
#define NB  2
#define THR 256

// ---------------- scratch (static __device__, allocation-free) --------------
static __device__ __half g_Xh[4096*1024], g_Xl[4096*1024];
static __device__ __half g_Wth[3*1024*1024], g_Wtl[3*1024*1024];   // [z][n][k]
static __device__ __half g_Qh[HB*SEQ*DH], g_Ql[HB*SEQ*DH];         // [hb][s][dh]
static __device__ __half g_Kh[HB*SEQ*DH], g_Kl[HB*SEQ*DH];
static __device__ __half g_Vh[HB*SEQ*DH];

// ---------------- helpers ---------------------------------------------------
__device__ __forceinline__ uint32_t s2u(const void* p){
    uint32_t a;
    asm("{ .reg .u64 t; cvta.to.shared.u64 t, %1; cvt.u32.u64 %0, t; }" : "=r"(a) : "l"(p));
    return a;
}
#define CPA(s,g) asm volatile("cp.async.cg.shared.global [%0], [%1], 16;" :: "r"(s), "l"(g))
#define CPA_COMMIT() asm volatile("cp.async.commit_group;" ::: "memory")
#define CPA_WAIT(n)  asm volatile("cp.async.wait_group %0;" :: "n"(n) : "memory")

__device__ __forceinline__ void ldsm4(uint32_t* r, uint32_t a){
    asm volatile("ldmatrix.sync.aligned.m8n8.x4.shared.b16 {%0,%1,%2,%3}, [%4];"
        : "=r"(r[0]), "=r"(r[1]), "=r"(r[2]), "=r"(r[3]) : "r"(a));
}
__device__ __forceinline__ void ldsm4t(uint32_t* r, uint32_t a){
    asm volatile("ldmatrix.sync.aligned.m8n8.x4.trans.shared.b16 {%0,%1,%2,%3}, [%4];"
        : "=r"(r[0]), "=r"(r[1]), "=r"(r[2]), "=r"(r[3]) : "r"(a));
}
__device__ __forceinline__ void mma16816(float* c, const uint32_t* a, uint32_t b0, uint32_t b1){
    asm volatile("mma.sync.aligned.m16n8k16.row.col.f32.f16.f16.f32 "
        "{%0,%1,%2,%3}, {%4,%5,%6,%7}, {%8,%9}, {%0,%1,%2,%3};"
        : "+f"(c[0]), "+f"(c[1]), "+f"(c[2]), "+f"(c[3])
        : "r"(a[0]), "r"(a[1]), "r"(a[2]), "r"(a[3]), "r"(b0), "r"(b1));
}
__device__ __forceinline__ uint32_t swa(uint32_t base, int r, int cb){
    uint32_t off = (uint32_t)r * 128u + (uint32_t)cb;
    return base + (off ^ ((off >> 3) & 0x70));
}
__device__ __forceinline__ void split2(float x, float y, uint32_t& hi, uint32_t& lo){
    __half hx = __float2half_rn(x), hy = __float2half_rn(y);
    __half lx = __float2half_rn(x - __half2float(hx));
    __half ly = __float2half_rn(y - __half2float(hy));
    __half2 H = __halves2half2(hx, hy), L = __halves2half2(lx, ly);
    hi = *(uint32_t*)&H; lo = *(uint32_t*)&L;
}
__device__ __forceinline__ void fsplit(float x, __half& h, __half& l){
    h = __float2half_rn(x);
    l = __float2half_rn(x - __half2float(h));
}
__device__ __forceinline__ uint32_t pack_h2(float x, float y){
    __half2 p = __floats2half2_rn(x, y);
    return *(uint32_t*)&p;
}
__device__ __forceinline__ void load_tile(uint32_t sdst, const __half* g,
                                          int rows, int gstride){
    for (int i = threadIdx.x; i < rows * 8; i += THR){
        int r = i >> 3, c = i & 7;
        uint32_t off = (uint32_t)r * 128u + (uint32_t)c * 16u;
        uint32_t sw  = off ^ ((off >> 3) & 0x70);
        CPA(sdst + sw, (const char*)(g + (size_t)r * gstride) + c * 16);
    }
}

// ---------------- prep ------------------------------------------------------
__global__ void __launch_bounds__(256) k_splitX(const float4* __restrict__ X){
    int i = blockIdx.x * 256 + threadIdx.x;
    float4 v = X[i];
    uint32_t h0, l0, h1, l1;
    split2(v.x, v.y, h0, l0);
    split2(v.z, v.w, h1, l1);
    ((uint2*)g_Xh)[i] = make_uint2(h0, h1);
    ((uint2*)g_Xl)[i] = make_uint2(l0, l1);
}

__global__ void __launch_bounds__(256) k_splitW(const float* __restrict__ Wq,
                                                const float* __restrict__ Wk,
                                                const float* __restrict__ Wv){
    const int z = blockIdx.z;
    const float* __restrict__ W = (z == 0) ? Wq : (z == 1) ? Wk : Wv;
    __shared__ float t[32][33];
    int tx = threadIdx.x, ty = threadIdx.y;      // (32,8)
    int bx = blockIdx.x * 32, by = blockIdx.y * 32;
#pragma unroll
    for (int i = 0; i < 32; i += 8)
        t[ty + i][tx] = W[(size_t)(by + ty + i) * DIM + bx + tx];
    __syncthreads();
#pragma unroll
    for (int i = 0; i < 32; i += 8){
        int n = bx + ty + i, k = by + tx;
        __half h, l; fsplit(t[tx][ty + i], h, l);
        size_t o = (size_t)z * DIM * DIM + (size_t)n * DIM + k;
        g_Wth[o] = h; g_Wtl[o] = l;
    }
}

// ---------------- QKV: 128x64 CTA tile, 32x32 warp tile, 2-stage ------------
#define QKV_STAGE 49152
#define QKV_SMEM  (2 * QKV_STAGE)
__global__ void __launch_bounds__(256, 2) k_qkv_mma(){
    extern __shared__ __align__(1024) char smraw[];
    uint32_t sbase = s2u(smraw);
    const int tid = threadIdx.x, w = tid >> 5, lane = tid & 31;
    const int z  = blockIdx.z;
    const int bm = blockIdx.y * 128;
    const int bn = blockIdx.x * 64;

    const __half* Ah = g_Xh + (size_t)bm * DIM;
    const __half* Al = g_Xl + (size_t)bm * DIM;
    const __half* Bh = g_Wth + (size_t)z * DIM * DIM + (size_t)bn * DIM;
    const __half* Bl = g_Wtl + (size_t)z * DIM * DIM + (size_t)bn * DIM;

    float c[2][4][4];
#pragma unroll
    for (int a = 0; a < 2; a++)
#pragma unroll
        for (int b = 0; b < 4; b++)
#pragma unroll
            for (int d = 0; d < 4; d++) c[a][b][d] = 0.f;

    const int m0 = (w & 3) * 32, n0 = (w >> 2) * 32;
    const int NT = DIM / 64;   // 16
    const bool full = (z < 2);   // V tolerates 2-term split

    auto stage_load = [&](int kt){
        uint32_t buf = sbase + (uint32_t)(kt & 1) * QKV_STAGE;
        load_tile(buf,         Ah + kt * 64, 128, DIM);
        load_tile(buf + 16384, Al + kt * 64, 128, DIM);
        load_tile(buf + 32768, Bh + kt * 64,  64, DIM);
        load_tile(buf + 40960, Bl + kt * 64,  64, DIM);
    };
    stage_load(0); CPA_COMMIT();
    stage_load(1); CPA_COMMIT();

    for (int kt = 0; kt < NT; kt++){
        CPA_WAIT(1);
        __syncthreads();
        uint32_t buf = sbase + (uint32_t)(kt & 1) * QKV_STAGE;
        const uint32_t sAh = buf, sAl = buf + 16384;
        const uint32_t sBh = buf + 32768, sBl = buf + 40960;
#pragma unroll
        for (int kk = 0; kk < 4; kk++){
            uint32_t aH[2][4], aL[2][4];
            int cb = kk * 32 + (lane >> 4) * 16;
#pragma unroll
            for (int mt = 0; mt < 2; mt++){
                int rr = m0 + mt * 16 + (lane & 15);
                ldsm4(aH[mt], swa(sAh, rr, cb));
                ldsm4(aL[mt], swa(sAl, rr, cb));
            }
#pragma unroll
            for (int nt = 0; nt < 2; nt++){
                uint32_t bH[4], bL[4];
                int rr = n0 + nt * 16 + (lane & 15);
                ldsm4(bH, swa(sBh, rr, cb));
                ldsm4(bL, swa(sBl, rr, cb));
#pragma unroll
                for (int mt = 0; mt < 2; mt++){
                    mma16816(c[mt][2*nt],   aH[mt], bH[0], bH[2]);
                    mma16816(c[mt][2*nt+1], aH[mt], bH[1], bH[3]);
                    mma16816(c[mt][2*nt],   aH[mt], bL[0], bL[2]);
                    mma16816(c[mt][2*nt+1], aH[mt], bL[1], bL[3]);
                    if (full){
                        mma16816(c[mt][2*nt],   aL[mt], bH[0], bH[2]);
                        mma16816(c[mt][2*nt+1], aL[mt], bH[1], bH[3]);
                    }
                }
            }
        }
        __syncthreads();
        if (kt + 2 < NT) stage_load(kt + 2);
        CPA_COMMIT();
    }

    // Q gets 0.125 * log2(e) so flash can use exp2 directly.
    const float sc = (z == 0) ? 0.125f * 1.4426950408889634f : 1.0f;
#pragma unroll
    for (int mt = 0; mt < 2; mt++){
#pragma unroll
        for (int nt = 0; nt < 4; nt++){
            int n = bn + n0 + nt * 8 + (lane & 3) * 2;
            int h = n >> 6, d = n & 63;
#pragma unroll
            for (int half = 0; half < 2; half++){
                int m = bm + m0 + mt * 16 + (lane >> 2) + half * 8;
                int bb = m >> 11, s = m & (SEQ - 1);
                size_t o = ((size_t)(h * NB + bb) * SEQ + s) * DH + d;
                if (z == 2){
                    *(uint32_t*)(g_Vh + o) = pack_h2(c[mt][nt][half*2], c[mt][nt][half*2+1]);
                } else {
                    uint32_t hi, lo;
                    split2(c[mt][nt][half*2] * sc, c[mt][nt][half*2+1] * sc, hi, lo);
                    __half* Gh = (z == 0) ? g_Qh : g_Kh;
                    __half* Gl = (z == 0) ? g_Ql : g_Kl;
                    *(uint32_t*)(Gh + o) = hi;
                    *(uint32_t*)(Gl + o) = lo;
                }
            }
        }
    }
}

// ---------------- fused flash attention: 64 q-rows, 256 thr, 2 CTAs/SM ------
// (R12 geometry — best measured.) Warp (wq,wg): q rows [wq*16,+16),
// keys [wg*32,+32) of each 64-key tile. 3-stage ring, split-K merge at end.
#define FA_STAGE 24576
#define FA_SMEM  (16384 + 3 * FA_STAGE)
__global__ void __launch_bounds__(256, 2) k_flash(float* __restrict__ out){
    extern __shared__ __align__(1024) char smraw[];
    uint32_t sbase = s2u(smraw);
    const int tid = threadIdx.x, w = tid >> 5, lane = tid & 31;
    const int wq = w & 3, wg = w >> 2;
    const int z  = blockIdx.y;
    const int bm = blockIdx.x * 64;

    const uint32_t sQh = sbase, sQl = sbase + 8192;
    const uint32_t stg = sbase + 16384;
    const uint32_t ONES = 0x3C003C00u;   // half2(1.0, 1.0)

    const __half* Kh = g_Kh + (size_t)z * SEQ * DH;
    const __half* Kl = g_Kl + (size_t)z * SEQ * DH;
    const __half* Vh = g_Vh + (size_t)z * SEQ * DH;

    auto stage_load = [&](int kt){
        uint32_t buf = stg + (uint32_t)(kt % 3) * FA_STAGE;
        load_tile(buf,         Kh + (size_t)kt * 64 * DH, 64, DH);
        load_tile(buf +  8192, Kl + (size_t)kt * 64 * DH, 64, DH);
        load_tile(buf + 16384, Vh + (size_t)kt * 64 * DH, 64, DH);
    };
    load_tile(sQh, g_Qh + ((size_t)z * SEQ + bm) * DH, 64, DH);
    load_tile(sQl, g_Ql + ((size_t)z * SEQ + bm) * DH, 64, DH);
    stage_load(0); CPA_COMMIT();
    stage_load(1); CPA_COMMIT();

    float co[8][4];
#pragma unroll
    for (int i = 0; i < 8; i++)
#pragma unroll
        for (int j = 0; j < 4; j++) co[i][j] = 0.f;
    float cl[4] = {0.f, 0.f, 0.f, 0.f};
    float m0 = -1e30f, m1 = -1e30f;

    uint32_t qH[4][4];   // hoisted Q hi fragments

    const int NT = SEQ / 64;   // 32
    for (int kt = 0; kt < NT; kt++){
        CPA_WAIT(1);
        __syncthreads();
        if (kt + 2 < NT) stage_load(kt + 2);
        CPA_COMMIT();

        if (kt == 0){
#pragma unroll
            for (int kk = 0; kk < 4; kk++){
                int rr = wq * 16 + (lane & 15);
                int cb = kk * 32 + (lane >> 4) * 16;
                ldsm4(qH[kk], swa(sQh, rr, cb));
            }
        }

        uint32_t bufC = stg + (uint32_t)(kt % 3) * FA_STAGE;
        const uint32_t sKh = bufC, sKl = bufC + 8192;
        const uint32_t sVh = bufC + 16384;

        // ---- S = Q @ K^T (16 q-rows x 32 keys per warp, 3-term fp32) ----
        float cs[4][4];
#pragma unroll
        for (int t = 0; t < 4; t++)
#pragma unroll
            for (int j = 0; j < 4; j++) cs[t][j] = 0.f;
#pragma unroll
        for (int kk = 0; kk < 4; kk++){
            uint32_t qL[4];
            {
                int rr = wq * 16 + (lane & 15);
                int cb = kk * 32 + (lane >> 4) * 16;
                ldsm4(qL, swa(sQl, rr, cb));
            }
#pragma unroll
            for (int nq = 0; nq < 2; nq++){
                uint32_t bH[4], bL[4];
                int rr = wg * 32 + nq * 16 + (lane & 15);
                int cb = kk * 32 + (lane >> 4) * 16;
                ldsm4(bH, swa(sKh, rr, cb));
                ldsm4(bL, swa(sKl, rr, cb));
                mma16816(cs[2*nq],   qH[kk], bH[0], bH[2]);
                mma16816(cs[2*nq+1], qH[kk], bH[1], bH[3]);
                mma16816(cs[2*nq],   qH[kk], bL[0], bL[2]);
                mma16816(cs[2*nq+1], qH[kk], bL[1], bL[3]);
                mma16816(cs[2*nq],   qL,     bH[0], bH[2]);
                mma16816(cs[2*nq+1], qL,     bH[1], bH[3]);
            }
        }

        // ---- online softmax in base-2 (rows r0=lane>>2, r1=r0+8) ----
        float mx0 = -1e30f, mx1 = -1e30f;
#pragma unroll
        for (int t = 0; t < 4; t++){
            mx0 = fmaxf(mx0, fmaxf(cs[t][0], cs[t][1]));
            mx1 = fmaxf(mx1, fmaxf(cs[t][2], cs[t][3]));
        }
        mx0 = fmaxf(mx0, __shfl_xor_sync(0xffffffffu, mx0, 1));
        mx0 = fmaxf(mx0, __shfl_xor_sync(0xffffffffu, mx0, 2));
        mx1 = fmaxf(mx1, __shfl_xor_sync(0xffffffffu, mx1, 1));
        mx1 = fmaxf(mx1, __shfl_xor_sync(0xffffffffu, mx1, 2));

        float mn0 = fmaxf(m0, mx0), mn1 = fmaxf(m1, mx1);
        bool same = (mn0 == m0) && (mn1 == m1);
        if (!__all_sync(0xffffffffu, same)){
            float sc0 = exp2f(m0 - mn0), sc1 = exp2f(m1 - mn1);
            m0 = mn0; m1 = mn1;
            cl[0] *= sc0; cl[2] *= sc1;
#pragma unroll
            for (int nt = 0; nt < 8; nt++){
                co[nt][0] *= sc0; co[nt][1] *= sc0;
                co[nt][2] *= sc1; co[nt][3] *= sc1;
            }
        }

#pragma unroll
        for (int t = 0; t < 4; t++){
            cs[t][0] = exp2f(cs[t][0] - m0);
            cs[t][1] = exp2f(cs[t][1] - m0);
            cs[t][2] = exp2f(cs[t][2] - m1);
            cs[t][3] = exp2f(cs[t][3] - m1);
        }

        // ---- O += P(fp16) @ V(fp16); l += P @ ones ----
#pragma unroll
        for (int kc = 0; kc < 2; kc++){
            uint32_t aP[4];
            aP[0] = pack_h2(cs[2*kc][0],   cs[2*kc][1]);
            aP[1] = pack_h2(cs[2*kc][2],   cs[2*kc][3]);
            aP[2] = pack_h2(cs[2*kc+1][0], cs[2*kc+1][1]);
            aP[3] = pack_h2(cs[2*kc+1][2], cs[2*kc+1][3]);
            mma16816(cl, aP, ONES, ONES);
#pragma unroll
            for (int nq = 0; nq < 4; nq++){
                uint32_t bH[4];
                int rr = wg * 32 + kc * 16 + ((lane >> 4) & 1) * 8 + (lane & 7);
                int cb = (nq * 16 + ((lane >> 3) & 1) * 8) * 2;
                ldsm4t(bH, swa(sVh, rr, cb));
                mma16816(co[2*nq],   aP, bH[0], bH[2]);
                mma16816(co[2*nq+1], aP, bH[1], bH[3]);
            }
        }
    }

    float l0 = cl[0], l1 = cl[2];

    // ---- split-K merge across wg pairs (exchange via smem) ----
    CPA_WAIT(0);
    __syncthreads();
    float* ex = (float*)smraw;
    float* p = ex + ((size_t)(wq * 32 + lane)) * 37;
    if (wg == 1){
#pragma unroll
        for (int i = 0; i < 8; i++)
#pragma unroll
            for (int j = 0; j < 4; j++) p[i*4 + j] = co[i][j];
        p[32] = m0; p[33] = m1; p[34] = l0; p[35] = l1;
    }
    __syncthreads();
    if (wg == 0){
        float m0b = p[32], m1b = p[33], l0b = p[34], l1b = p[35];
        float mm0 = fmaxf(m0, m0b), mm1 = fmaxf(m1, m1b);
        float a0 = exp2f(m0 - mm0), b0 = exp2f(m0b - mm0);
        float a1 = exp2f(m1 - mm1), b1 = exp2f(m1b - mm1);
        float inv0 = 1.f / (l0 * a0 + l0b * b0);
        float inv1 = 1.f / (l1 * a1 + l1b * b1);

        const int r0 = bm + wq * 16 + (lane >> 2);
#pragma unroll
        for (int nt = 0; nt < 8; nt++){
            int n = nt * 8 + (lane & 3) * 2;
            float* d0 = out + ((size_t)z * SEQ + r0) * DH + n;
            float* d1 = out + ((size_t)z * SEQ + r0 + 8) * DH + n;
            float o00 = (co[nt][0] * a0 + p[nt*4+0] * b0) * inv0;
            float o01 = (co[nt][1] * a0 + p[nt*4+1] * b0) * inv0;
            float o10 = (co[nt][2] * a1 + p[nt*4+2] * b1) * inv1;
            float o11 = (co[nt][3] * a1 + p[nt*4+3] * b1) * inv1;
            *(float2*)d0 = make_float2(o00, o01);
            *(float2*)d1 = make_float2(o10, o11);
        }
    }
}

// ---------------------------------------------------------------------------
extern "C" void kernel_launch(void* const* d_in, const int* in_sizes, int n_in,
                              void* d_out, int out_size)
{
    const float* X  = (const float*)d_in[0];
    const float* Wq = (const float*)d_in[1];
    const float* Wk = (const float*)d_in[2];
    const float* Wv = (const float*)d_in[3];
    float* out = (float*)d_out;

    cudaFuncSetAttribute(k_qkv_mma, cudaFuncAttributeMaxDynamicSharedMemorySize, QKV_SMEM);
    cudaFuncSetAttribute(k_flash,   cudaFuncAttributeMaxDynamicSharedMemorySize, FA_SMEM);

    k_splitX <<<4096, 256>>>((const float4*)X);
    k_splitW <<<dim3(32, 32, 3), dim3(32, 8)>>>(Wq, Wk, Wv);
    k_qkv_mma<<<dim3(16, 32, 3), THR, QKV_SMEM>>>();
    k_flash  <<<dim3(SEQ / 64, HB), THR, FA_SMEM>>>(out);
}

// round 16
// speedup vs baseline: 1.6829x; 1.0907x over previous
#include <cuda_runtime.h>
#include <cuda_fp16.h>
#include <cstdint>

#define SEQ 2048
#define DIM 1024
#define DH  64
#define HB  32
#define NB  2
#define THR 256

// ---------------- scratch (static __device__, allocation-free) --------------
static __device__ __half g_Xh[4096*1024], g_Xl[4096*1024];
static __device__ __half g_Wth[3*1024*1024], g_Wtl[3*1024*1024];   // [z][n][k]
static __device__ __half g_Qh[HB*SEQ*DH], g_Ql[HB*SEQ*DH];         // [hb][s][dh]
static __device__ __half g_Kh[HB*SEQ*DH], g_Kl[HB*SEQ*DH];
static __device__ __half g_Vh[HB*SEQ*DH];

// ---------------- helpers ---------------------------------------------------
__device__ __forceinline__ uint32_t s2u(const void* p){
    uint32_t a;
    asm("{ .reg .u64 t; cvta.to.shared.u64 t, %1; cvt.u32.u64 %0, t; }" : "=r"(a) : "l"(p));
    return a;
}
#define CPA(s,g) asm volatile("cp.async.cg.shared.global [%0], [%1], 16;" :: "r"(s), "l"(g))
#define CPA_COMMIT() asm volatile("cp.async.commit_group;" ::: "memory")
#define CPA_WAIT(n)  asm volatile("cp.async.wait_group %0;" :: "n"(n) : "memory")

__device__ __forceinline__ void ldsm4(uint32_t* r, uint32_t a){
    asm volatile("ldmatrix.sync.aligned.m8n8.x4.shared.b16 {%0,%1,%2,%3}, [%4];"
        : "=r"(r[0]), "=r"(r[1]), "=r"(r[2]), "=r"(r[3]) : "r"(a));
}
__device__ __forceinline__ void ldsm4t(uint32_t* r, uint32_t a){
    asm volatile("ldmatrix.sync.aligned.m8n8.x4.trans.shared.b16 {%0,%1,%2,%3}, [%4];"
        : "=r"(r[0]), "=r"(r[1]), "=r"(r[2]), "=r"(r[3]) : "r"(a));
}
__device__ __forceinline__ void mma16816(float* c, const uint32_t* a, uint32_t b0, uint32_t b1){
    asm volatile("mma.sync.aligned.m16n8k16.row.col.f32.f16.f16.f32 "
        "{%0,%1,%2,%3}, {%4,%5,%6,%7}, {%8,%9}, {%0,%1,%2,%3};"
        : "+f"(c[0]), "+f"(c[1]), "+f"(c[2]), "+f"(c[3])
        : "r"(a[0]), "r"(a[1]), "r"(a[2]), "r"(a[3]), "r"(b0), "r"(b1));
}
__device__ __forceinline__ uint32_t swa(uint32_t base, int r, int cb){
    uint32_t off = (uint32_t)r * 128u + (uint32_t)cb;
    return base + (off ^ ((off >> 3) & 0x70));
}
__device__ __forceinline__ void split2(float x, float y, uint32_t& hi, uint32_t& lo){
    __half hx = __float2half_rn(x), hy = __float2half_rn(y);
    __half lx = __float2half_rn(x - __half2float(hx));
    __half ly = __float2half_rn(y - __half2float(hy));
    __half2 H = __halves2half2(hx, hy), L = __halves2half2(lx, ly);
    hi = *(uint32_t*)&H; lo = *(uint32_t*)&L;
}
__device__ __forceinline__ void fsplit(float x, __half& h, __half& l){
    h = __float2half_rn(x);
    l = __float2half_rn(x - __half2float(h));
}
__device__ __forceinline__ uint32_t pack_h2(float x, float y){
    __half2 p = __floats2half2_rn(x, y);
    return *(uint32_t*)&p;
}
__device__ __forceinline__ void load_tile(uint32_t sdst, const __half* g,
                                          int rows, int gstride){
    for (int i = threadIdx.x; i < rows * 8; i += THR){
        int r = i >> 3, c = i & 7;
        uint32_t off = (uint32_t)r * 128u + (uint32_t)c * 16u;
        uint32_t sw  = off ^ ((off >> 3) & 0x70);
        CPA(sdst + sw, (const char*)(g + (size_t)r * gstride) + c * 16);
    }
}

// ---------------- prep ------------------------------------------------------
__global__ void __launch_bounds__(256) k_splitX(const float4* __restrict__ X){
    int i = blockIdx.x * 256 + threadIdx.x;
    float4 v = X[i];
    uint32_t h0, l0, h1, l1;
    split2(v.x, v.y, h0, l0);
    split2(v.z, v.w, h1, l1);
    ((uint2*)g_Xh)[i] = make_uint2(h0, h1);
    ((uint2*)g_Xl)[i] = make_uint2(l0, l1);
}

__global__ void __launch_bounds__(256) k_splitW(const float* __restrict__ Wq,
                                                const float* __restrict__ Wk,
                                                const float* __restrict__ Wv){
    const int z = blockIdx.z;
    const float* __restrict__ W = (z == 0) ? Wq : (z == 1) ? Wk : Wv;
    __shared__ float t[32][33];
    int tx = threadIdx.x, ty = threadIdx.y;      // (32,8)
    int bx = blockIdx.x * 32, by = blockIdx.y * 32;
#pragma unroll
    for (int i = 0; i < 32; i += 8)
        t[ty + i][tx] = W[(size_t)(by + ty + i) * DIM + bx + tx];
    __syncthreads();
#pragma unroll
    for (int i = 0; i < 32; i += 8){
        int n = bx + ty + i, k = by + tx;
        __half h, l; fsplit(t[tx][ty + i], h, l);
        size_t o = (size_t)z * DIM * DIM + (size_t)n * DIM + k;
        g_Wth[o] = h; g_Wtl[o] = l;
    }
}

// ---------------- QKV: 128x64 CTA tile, 32x32 warp tile, 2-stage ------------
#define QKV_STAGE 49152
#define QKV_SMEM  (2 * QKV_STAGE)
__global__ void __launch_bounds__(256, 2) k_qkv_mma(){
    extern __shared__ __align__(1024) char smraw[];
    uint32_t sbase = s2u(smraw);
    const int tid = threadIdx.x, w = tid >> 5, lane = tid & 31;
    const int z  = blockIdx.z;
    const int bm = blockIdx.y * 128;
    const int bn = blockIdx.x * 64;

    const char* pAh = (const char*)(g_Xh + (size_t)bm * DIM);
    const char* pAl = (const char*)(g_Xl + (size_t)bm * DIM);
    const char* pBh = (const char*)(g_Wth + (size_t)z * DIM * DIM + (size_t)bn * DIM);
    const char* pBl = (const char*)(g_Wtl + (size_t)z * DIM * DIM + (size_t)bn * DIM);

    float c[2][4][4];
#pragma unroll
    for (int a = 0; a < 2; a++)
#pragma unroll
        for (int b = 0; b < 4; b++)
#pragma unroll
            for (int d = 0; d < 4; d++) c[a][b][d] = 0.f;

    const int m0 = (w & 3) * 32, n0 = (w >> 2) * 32;
    const int NT = DIM / 64;   // 16
    const bool full = (z < 2);   // V tolerates 2-term split

    // Precomputed cp.async addressing.
    // Tile-local offset for row r0 = tid>>3, chunk c0 = (tid&7)*16:
    //   off0 = r0*128 + c0; swz = swizzle(off0).
    // Row-group step +32 rows = +4096 bytes (bit 12) leaves swizzle bits
    // (7..9) unchanged => sw(off0 + 4096*s) = swz + 4096*s.
    // Global: rows stride DIM*2 = 2048 B => byte off = r*2048 + c0;
    // row-group step = 65536 B; k-step (64 halfs) = 128 B.
    const uint32_t r0   = (uint32_t)(tid >> 3);
    const uint32_t c0   = (uint32_t)(tid & 7) * 16u;
    const uint32_t off0 = r0 * 128u + c0;
    const uint32_t swz  = off0 ^ ((off0 >> 3) & 0x70);
    const uint32_t gof  = r0 * 2048u + c0;

    auto stage_load = [&](int kt){
        uint32_t buf = sbase + (uint32_t)(kt & 1) * QKV_STAGE;
        uint32_t gb  = (uint32_t)kt * 128u + gof;
#pragma unroll
        for (uint32_t s = 0; s < 4; s++){
            CPA(buf + swz + s * 4096u,          pAh + gb + s * 65536u);
            CPA(buf + 16384u + swz + s * 4096u, pAl + gb + s * 65536u);
        }
#pragma unroll
        for (uint32_t s = 0; s < 2; s++){
            CPA(buf + 32768u + swz + s * 4096u, pBh + gb + s * 65536u);
            CPA(buf + 40960u + swz + s * 4096u, pBl + gb + s * 65536u);
        }
    };
    stage_load(0); CPA_COMMIT();
    stage_load(1); CPA_COMMIT();

    for (int kt = 0; kt < NT; kt++){
        CPA_WAIT(1);
        __syncthreads();
        uint32_t buf = sbase + (uint32_t)(kt & 1) * QKV_STAGE;
        const uint32_t sAh = buf, sAl = buf + 16384;
        const uint32_t sBh = buf + 32768, sBl = buf + 40960;
#pragma unroll
        for (int kk = 0; kk < 4; kk++){
            uint32_t aH[2][4], aL[2][4];
            int cb = kk * 32 + (lane >> 4) * 16;
#pragma unroll
            for (int mt = 0; mt < 2; mt++){
                int rr = m0 + mt * 16 + (lane & 15);
                ldsm4(aH[mt], swa(sAh, rr, cb));
                ldsm4(aL[mt], swa(sAl, rr, cb));
            }
#pragma unroll
            for (int nt = 0; nt < 2; nt++){
                uint32_t bH[4], bL[4];
                int rr = n0 + nt * 16 + (lane & 15);
                ldsm4(bH, swa(sBh, rr, cb));
                ldsm4(bL, swa(sBl, rr, cb));
#pragma unroll
                for (int mt = 0; mt < 2; mt++){
                    mma16816(c[mt][2*nt],   aH[mt], bH[0], bH[2]);
                    mma16816(c[mt][2*nt+1], aH[mt], bH[1], bH[3]);
                    mma16816(c[mt][2*nt],   aH[mt], bL[0], bL[2]);
                    mma16816(c[mt][2*nt+1], aH[mt], bL[1], bL[3]);
                    if (full){
                        mma16816(c[mt][2*nt],   aL[mt], bH[0], bH[2]);
                        mma16816(c[mt][2*nt+1], aL[mt], bH[1], bH[3]);
                    }
                }
            }
        }
        __syncthreads();
        if (kt + 2 < NT) stage_load(kt + 2);
        CPA_COMMIT();
    }

    // Q gets 0.125 * log2(e) so flash can use exp2 directly.
    const float sc = (z == 0) ? 0.125f * 1.4426950408889634f : 1.0f;
#pragma unroll
    for (int mt = 0; mt < 2; mt++){
#pragma unroll
        for (int nt = 0; nt < 4; nt++){
            int n = bn + n0 + nt * 8 + (lane & 3) * 2;
            int h = n >> 6, d = n & 63;
#pragma unroll
            for (int half = 0; half < 2; half++){
                int m = bm + m0 + mt * 16 + (lane >> 2) + half * 8;
                int bb = m >> 11, s = m & (SEQ - 1);
                size_t o = ((size_t)(h * NB + bb) * SEQ + s) * DH + d;
                if (z == 2){
                    *(uint32_t*)(g_Vh + o) = pack_h2(c[mt][nt][half*2], c[mt][nt][half*2+1]);
                } else {
                    uint32_t hi, lo;
                    split2(c[mt][nt][half*2] * sc, c[mt][nt][half*2+1] * sc, hi, lo);
                    __half* Gh = (z == 0) ? g_Qh : g_Kh;
                    __half* Gl = (z == 0) ? g_Ql : g_Kl;
                    *(uint32_t*)(Gh + o) = hi;
                    *(uint32_t*)(Gl + o) = lo;
                }
            }
        }
    }
}

// ---------------- fused flash attention: 64 q-rows, 256 thr, 2 CTAs/SM ------
// (R12 geometry.) Warp (wq,wg): q rows [wq*16,+16), keys [wg*32,+32) of each
// 64-key tile. 3-stage ring, split-K merge at end. Precomputed CPA addressing.
#define FA_STAGE 24576
#define FA_SMEM  (16384 + 3 * FA_STAGE)
__global__ void __launch_bounds__(256, 2) k_flash(float* __restrict__ out){
    extern __shared__ __align__(1024) char smraw[];
    uint32_t sbase = s2u(smraw);
    const int tid = threadIdx.x, w = tid >> 5, lane = tid & 31;
    const int wq = w & 3, wg = w >> 2;
    const int z  = blockIdx.y;
    const int bm = blockIdx.x * 64;

    const uint32_t sQh = sbase, sQl = sbase + 8192;
    const uint32_t stg = sbase + 16384;
    const uint32_t ONES = 0x3C003C00u;   // half2(1.0, 1.0)

    // K/V rows are globally contiguous (128 B/row): global byte offset equals
    // unswizzled tile offset; tile step = 64 rows * 128 B = 8192 B.
    const char* pKh = (const char*)(g_Kh + (size_t)z * SEQ * DH);
    const char* pKl = (const char*)(g_Kl + (size_t)z * SEQ * DH);
    const char* pVh = (const char*)(g_Vh + (size_t)z * SEQ * DH);

    const uint32_t r0   = (uint32_t)(tid >> 3);
    const uint32_t c0   = (uint32_t)(tid & 7) * 16u;
    const uint32_t off0 = r0 * 128u + c0;
    const uint32_t swz  = off0 ^ ((off0 >> 3) & 0x70);

    auto stage_load = [&](int kt){
        uint32_t buf = stg + (uint32_t)(kt % 3) * FA_STAGE;
        uint32_t gb  = (uint32_t)kt * 8192u + off0;
        CPA(buf + swz,                  pKh + gb);
        CPA(buf + swz + 4096u,          pKh + gb + 4096u);
        CPA(buf + 8192u + swz,          pKl + gb);
        CPA(buf + 8192u + swz + 4096u,  pKl + gb + 4096u);
        CPA(buf + 16384u + swz,         pVh + gb);
        CPA(buf + 16384u + swz + 4096u, pVh + gb + 4096u);
    };
    load_tile(sQh, g_Qh + ((size_t)z * SEQ + bm) * DH, 64, DH);
    load_tile(sQl, g_Ql + ((size_t)z * SEQ + bm) * DH, 64, DH);
    stage_load(0); CPA_COMMIT();
    stage_load(1); CPA_COMMIT();

    float co[8][4];
#pragma unroll
    for (int i = 0; i < 8; i++)
#pragma unroll
        for (int j = 0; j < 4; j++) co[i][j] = 0.f;
    float cl[4] = {0.f, 0.f, 0.f, 0.f};
    float m0 = -1e30f, m1 = -1e30f;

    uint32_t qH[4][4];   // hoisted Q hi fragments

    const int NT = SEQ / 64;   // 32
    for (int kt = 0; kt < NT; kt++){
        CPA_WAIT(1);
        __syncthreads();
        if (kt + 2 < NT) stage_load(kt + 2);
        CPA_COMMIT();

        if (kt == 0){
#pragma unroll
            for (int kk = 0; kk < 4; kk++){
                int rr = wq * 16 + (lane & 15);
                int cb = kk * 32 + (lane >> 4) * 16;
                ldsm4(qH[kk], swa(sQh, rr, cb));
            }
        }

        uint32_t bufC = stg + (uint32_t)(kt % 3) * FA_STAGE;
        const uint32_t sKh = bufC, sKl = bufC + 8192;
        const uint32_t sVh = bufC + 16384;

        // ---- S = Q @ K^T (16 q-rows x 32 keys per warp, 3-term fp32) ----
        float cs[4][4];
#pragma unroll
        for (int t = 0; t < 4; t++)
#pragma unroll
            for (int j = 0; j < 4; j++) cs[t][j] = 0.f;
#pragma unroll
        for (int kk = 0; kk < 4; kk++){
            uint32_t qL[4];
            {
                int rr = wq * 16 + (lane & 15);
                int cb = kk * 32 + (lane >> 4) * 16;
                ldsm4(qL, swa(sQl, rr, cb));
            }
#pragma unroll
            for (int nq = 0; nq < 2; nq++){
                uint32_t bH[4], bL[4];
                int rr = wg * 32 + nq * 16 + (lane & 15);
                int cb = kk * 32 + (lane >> 4) * 16;
                ldsm4(bH, swa(sKh, rr, cb));
                ldsm4(bL, swa(sKl, rr, cb));
                mma16816(cs[2*nq],   qH[kk], bH[0], bH[2]);
                mma16816(cs[2*nq+1], qH[kk], bH[1], bH[3]);
                mma16816(cs[2*nq],   qH[kk], bL[0], bL[2]);
                mma16816(cs[2*nq+1], qH[kk], bL[1], bL[3]);
                mma16816(cs[2*nq],   qL,     bH[0], bH[2]);
                mma16816(cs[2*nq+1], qL,     bH[1], bH[3]);
            }
        }

        // ---- online softmax in base-2 (rows r0=lane>>2, r1=r0+8) ----
        float mx0 = -1e30f, mx1 = -1e30f;
#pragma unroll
        for (int t = 0; t < 4; t++){
            mx0 = fmaxf(mx0, fmaxf(cs[t][0], cs[t][1]));
            mx1 = fmaxf(mx1, fmaxf(cs[t][2], cs[t][3]));
        }
        mx0 = fmaxf(mx0, __shfl_xor_sync(0xffffffffu, mx0, 1));
        mx0 = fmaxf(mx0, __shfl_xor_sync(0xffffffffu, mx0, 2));
        mx1 = fmaxf(mx1, __shfl_xor_sync(0xffffffffu, mx1, 1));
        mx1 = fmaxf(mx1, __shfl_xor_sync(0xffffffffu, mx1, 2));

        float mn0 = fmaxf(m0, mx0), mn1 = fmaxf(m1, mx1);
        bool same = (mn0 == m0) && (mn1 == m1);
        if (!__all_sync(0xffffffffu, same)){
            float sc0 = exp2f(m0 - mn0), sc1 = exp2f(m1 - mn1);
            m0 = mn0; m1 = mn1;
            cl[0] *= sc0; cl[2] *= sc1;
#pragma unroll
            for (int nt = 0; nt < 8; nt++){
                co[nt][0] *= sc0; co[nt][1] *= sc0;
                co[nt][2] *= sc1; co[nt][3] *= sc1;
            }
        }

#pragma unroll
        for (int t = 0; t < 4; t++){
            cs[t][0] = exp2f(cs[t][0] - m0);
            cs[t][1] = exp2f(cs[t][1] - m0);
            cs[t][2] = exp2f(cs[t][2] - m1);
            cs[t][3] = exp2f(cs[t][3] - m1);
        }

        // ---- O += P(fp16) @ V(fp16); l += P @ ones ----
#pragma unroll
        for (int kc = 0; kc < 2; kc++){
            uint32_t aP[4];
            aP[0] = pack_h2(cs[2*kc][0],   cs[2*kc][1]);
            aP[1] = pack_h2(cs[2*kc][2],   cs[2*kc][3]);
            aP[2] = pack_h2(cs[2*kc+1][0], cs[2*kc+1][1]);
            aP[3] = pack_h2(cs[2*kc+1][2], cs[2*kc+1][3]);
            mma16816(cl, aP, ONES, ONES);
#pragma unroll
            for (int nq = 0; nq < 4; nq++){
                uint32_t bH[4];
                int rr = wg * 32 + kc * 16 + ((lane >> 4) & 1) * 8 + (lane & 7);
                int cb = (nq * 16 + ((lane >> 3) & 1) * 8) * 2;
                ldsm4t(bH, swa(sVh, rr, cb));
                mma16816(co[2*nq],   aP, bH[0], bH[2]);
                mma16816(co[2*nq+1], aP, bH[1], bH[3]);
            }
        }
    }

    float l0 = cl[0], l1 = cl[2];

    // ---- split-K merge across wg pairs (exchange via smem) ----
    CPA_WAIT(0);
    __syncthreads();
    float* ex = (float*)smraw;
    float* p = ex + ((size_t)(wq * 32 + lane)) * 37;
    if (wg == 1){
#pragma unroll
        for (int i = 0; i < 8; i++)
#pragma unroll
            for (int j = 0; j < 4; j++) p[i*4 + j] = co[i][j];
        p[32] = m0; p[33] = m1; p[34] = l0; p[35] = l1;
    }
    __syncthreads();
    if (wg == 0){
        float m0b = p[32], m1b = p[33], l0b = p[34], l1b = p[35];
        float mm0 = fmaxf(m0, m0b), mm1 = fmaxf(m1, m1b);
        float a0 = exp2f(m0 - mm0), b0 = exp2f(m0b - mm0);
        float a1 = exp2f(m1 - mm1), b1 = exp2f(m1b - mm1);
        float inv0 = 1.f / (l0 * a0 + l0b * b0);
        float inv1 = 1.f / (l1 * a1 + l1b * b1);

        const int r0o = bm + wq * 16 + (lane >> 2);
#pragma unroll
        for (int nt = 0; nt < 8; nt++){
            int n = nt * 8 + (lane & 3) * 2;
            float* d0 = out + ((size_t)z * SEQ + r0o) * DH + n;
            float* d1 = out + ((size_t)z * SEQ + r0o + 8) * DH + n;
            float o00 = (co[nt][0] * a0 + p[nt*4+0] * b0) * inv0;
            float o01 = (co[nt][1] * a0 + p[nt*4+1] * b0) * inv0;
            float o10 = (co[nt][2] * a1 + p[nt*4+2] * b1) * inv1;
            float o11 = (co[nt][3] * a1 + p[nt*4+3] * b1) * inv1;
            *(float2*)d0 = make_float2(o00, o01);
            *(float2*)d1 = make_float2(o10, o11);
        }
    }
}

// ---------------------------------------------------------------------------
extern "C" void kernel_launch(void* const* d_in, const int* in_sizes, int n_in,
                              void* d_out, int out_size)
{
    const float* X  = (const float*)d_in[0];
    const float* Wq = (const float*)d_in[1];
    const float* Wk = (const float*)d_in[2];
    const float* Wv = (const float*)d_in[3];
    float* out = (float*)d_out;

    cudaFuncSetAttribute(k_qkv_mma, cudaFuncAttributeMaxDynamicSharedMemorySize, QKV_SMEM);
    cudaFuncSetAttribute(k_flash,   cudaFuncAttributeMaxDynamicSharedMemorySize, FA_SMEM);

    k_splitX <<<4096, 256>>>((const float4*)X);
    k_splitW <<<dim3(32, 32, 3), dim3(32, 8)>>>(Wq, Wk, Wv);
    k_qkv_mma<<<dim3(16, 32, 3), THR, QKV_SMEM>>>();
    k_flash  <<<dim3(SEQ / 64, HB), THR, FA_SMEM>>>(out);
}